// round 1
// baseline (speedup 1.0000x reference)
#include <cuda_runtime.h>
#include <math.h>

// Problem constants
#define B_   2
#define H_   64
#define W_   64
#define HW_  4096
#define M_   8192          // B*HW
#define C1_  768           // concat channels (layer 1 input)
#define C2_  256           // layer 2 input channels
#define K1_  6912          // C1*9
#define K2_  2304          // C2*9
#define OC_  256

// Static scratch (no allocations allowed)
__device__ float g_V[K1_ * M_];            // im2col / deform-gather matrix, K-major: V[k][pix]
__device__ float g_om[B_ * 27 * HW_];      // offset-conv output, NCHW
__device__ float g_h1[B_ * OC_ * HW_];     // layer-1 output, NCHW

// --------------------------------------------------------------------------
// im2col: V[(c*9+k)][b*HW + h*64 + w] = in[b][c][h+ky-1][w+kx-1]  (0-padded)
// in is either (x,msg1,msg2) concat (C=768) or g_h1 (C=256, in0==nullptr)
// --------------------------------------------------------------------------
__global__ void im2col_kernel(const float* __restrict__ in0,
                              const float* __restrict__ in1,
                              const float* __restrict__ in2,
                              int C) {
    int idx = blockIdx.x * blockDim.x + threadIdx.x;
    int total = C * 9 * M_;
    if (idx >= total) return;
    int p = idx & (M_ - 1);
    int r = idx >> 13;                 // r = c*9 + k
    int c = r / 9;
    int k = r - c * 9;
    int ky = k / 3 - 1, kx = k % 3 - 1;
    int b = p >> 12, hw = p & 4095;
    int h = hw >> 6, w = hw & 63;
    int y = h + ky, x = w + kx;
    float v = 0.f;
    if (y >= 0 && y < 64 && x >= 0 && x < 64) {
        const float* src;
        if (in0 == nullptr) src = g_h1;
        else src = (c < 256) ? in0 : ((c < 512) ? in1 : in2);
        v = src[((b << 8) + (c & 255)) * HW_ + y * 64 + x];
    }
    g_V[idx] = v;
}

// --------------------------------------------------------------------------
// Deform gather: for each (b,k,h,w) read offsets/mask from g_om, bilinear
// sample all C channels of the source image, write V[(c*9+k)][pix] = v*mask.
// grid.x = B*9*H, block = 256 (w in [0,64) x 4 channel groups)
// --------------------------------------------------------------------------
__global__ void gather_kernel(const float* __restrict__ in0,
                              const float* __restrict__ in1,
                              const float* __restrict__ in2,
                              int C) {
    int hb = blockIdx.x;
    int h  = hb & 63;
    int bk = hb >> 6;
    int k  = bk % 9;
    int b  = bk / 9;
    int w  = threadIdx.x & 63;
    int cq = threadIdx.x >> 6;       // 0..3

    int ombase = (b * 27) * HW_ + h * 64 + w;
    float dy = g_om[ombase + (2 * k) * HW_];
    float dx = g_om[ombase + (2 * k + 1) * HW_];
    float mk = g_om[ombase + (18 + k) * HW_];
    mk = 1.0f / (1.0f + expf(-mk));

    float ys = dy + (float)h + (float)(k / 3 - 1);
    float xs = dx + (float)w + (float)(k % 3 - 1);
    float y0f = floorf(ys), x0f = floorf(xs);
    float wy = ys - y0f, wx = xs - x0f;
    int y0 = (int)y0f, x0 = (int)x0f;
    int y1 = y0 + 1,  x1 = x0 + 1;
    float vy0 = (y0 >= 0 && y0 < 64) ? 1.f : 0.f;
    float vy1 = (y1 >= 0 && y1 < 64) ? 1.f : 0.f;
    float vx0 = (x0 >= 0 && x0 < 64) ? 1.f : 0.f;
    float vx1 = (x1 >= 0 && x1 < 64) ? 1.f : 0.f;
    int y0c = min(max(y0, 0), 63), y1c = min(max(y1, 0), 63);
    int x0c = min(max(x0, 0), 63), x1c = min(max(x1, 0), 63);
    float w00 = (1.f - wy) * (1.f - wx) * vy0 * vx0;
    float w01 = (1.f - wy) * wx * vy0 * vx1;
    float w10 = wy * (1.f - wx) * vy1 * vx0;
    float w11 = wy * wx * vy1 * vx1;
    int i00 = y0c * 64 + x0c, i01 = y0c * 64 + x1c;
    int i10 = y1c * 64 + x0c, i11 = y1c * 64 + x1c;

    int outbase = k * M_ + b * HW_ + h * 64 + w;
    for (int c = cq; c < C; c += 4) {
        const float* src;
        if (in0 == nullptr) src = g_h1;
        else src = (c < 256) ? in0 : ((c < 512) ? in1 : in2);
        const float* p = src + ((b << 8) + (c & 255)) * HW_;
        float v = w00 * p[i00] + w01 * p[i01] + w10 * p[i10] + w11 * p[i11];
        g_V[outbase + c * 9 * M_] = v * mk;
    }
}

// --------------------------------------------------------------------------
// Tiled SIMT GEMM:  Out[pix][n] = sum_k V[k][pix] * Wt[n][k]
// MODE 0: out = g_om  (acc + bias[n]),                  N=27 channels NCHW
// MODE 1: out = g_h1  (bn+relu),                        N=256 NCHW
// MODE 2: out = param (bn+relu, +resid*gamma, leaky),   N=256 NCHW
// --------------------------------------------------------------------------
template<int BM, int BN, int TM, int TN, int MODE>
__global__ void gemm_kernel(const float* __restrict__ Wt,
                            const float* __restrict__ bias,
                            int N, int K,
                            float* __restrict__ outp,
                            const float* __restrict__ bng,
                            const float* __restrict__ bnb,
                            const float* __restrict__ bnm,
                            const float* __restrict__ bnv,
                            const float* __restrict__ resid,
                            const float* __restrict__ gamma) {
    constexpr int BK = 16;
    constexpr int TX = BN / TN;   // threads along n
    __shared__ float As[BK][BM];
    __shared__ float Bs[BK][BN + 1];
    int tid = threadIdx.x;
    int tx = tid % TX;
    int ty = tid / TX;
    int m0 = blockIdx.x * BM;
    int n0 = blockIdx.y * BN;

    float acc[TM][TN];
    #pragma unroll
    for (int i = 0; i < TM; i++)
        #pragma unroll
        for (int j = 0; j < TN; j++) acc[i][j] = 0.f;

    for (int k0 = 0; k0 < K; k0 += BK) {
        #pragma unroll
        for (int i = tid; i < BM * BK; i += 256) {
            int mm = i % BM; int kk = i / BM;
            As[kk][mm] = g_V[(k0 + kk) * M_ + m0 + mm];
        }
        #pragma unroll
        for (int i = tid; i < BK * BN; i += 256) {
            int kk = i % BK; int nn = i / BK;
            int n = n0 + nn;
            Bs[kk][nn] = (n < N) ? Wt[n * K + k0 + kk] : 0.f;
        }
        __syncthreads();
        #pragma unroll
        for (int kk = 0; kk < BK; kk++) {
            float a[TM], bv[TN];
            #pragma unroll
            for (int i = 0; i < TM; i++) a[i] = As[kk][ty * TM + i];
            #pragma unroll
            for (int j = 0; j < TN; j++) bv[j] = Bs[kk][tx * TN + j];
            #pragma unroll
            for (int i = 0; i < TM; i++)
                #pragma unroll
                for (int j = 0; j < TN; j++)
                    acc[i][j] = fmaf(a[i], bv[j], acc[i][j]);
        }
        __syncthreads();
    }

    float gam = (MODE == 2) ? gamma[0] : 0.f;
    float* dst = (MODE == 0) ? g_om : ((MODE == 1) ? g_h1 : outp);

    #pragma unroll
    for (int j = 0; j < TN; j++) {
        int n = n0 + tx * TN + j;
        if (n >= N) continue;
        float scale = 0.f, shift = 0.f, bs = 0.f;
        if (MODE >= 1) {
            scale = bng[n] / sqrtf(bnv[n] + 1e-5f);
            shift = bnb[n] - bnm[n] * scale;
        } else {
            bs = bias[n];
        }
        #pragma unroll
        for (int i = 0; i < TM; i++) {
            int m = m0 + ty * TM + i;
            int b = m >> 12; int hw = m & 4095;
            float v = acc[i][j];
            int oidx = (b * N + n) * HW_ + hw;
            if (MODE == 0) {
                dst[oidx] = v + bs;
            } else if (MODE == 1) {
                dst[oidx] = fmaxf(v * scale + shift, 0.f);
            } else {
                float t = fmaxf(v * scale + shift, 0.f);
                float o = resid[oidx] + gam * t;
                dst[oidx] = (o >= 0.f) ? o : 0.01f * o;
            }
        }
    }
}

// --------------------------------------------------------------------------
extern "C" void kernel_launch(void* const* d_in, const int* in_sizes, int n_in,
                              void* d_out, int out_size) {
    const float* x      = (const float*)d_in[0];
    const float* msg1   = (const float*)d_in[1];
    const float* msg2   = (const float*)d_in[2];
    const float* w_off1 = (const float*)d_in[3];
    const float* b_off1 = (const float*)d_in[4];
    const float* w1     = (const float*)d_in[5];
    const float* bn1g   = (const float*)d_in[6];
    const float* bn1b   = (const float*)d_in[7];
    const float* bn1m   = (const float*)d_in[8];
    const float* bn1v   = (const float*)d_in[9];
    const float* w_off2 = (const float*)d_in[10];
    const float* b_off2 = (const float*)d_in[11];
    const float* w2     = (const float*)d_in[12];
    const float* bn2g   = (const float*)d_in[13];
    const float* bn2b   = (const float*)d_in[14];
    const float* bn2m   = (const float*)d_in[15];
    const float* bn2v   = (const float*)d_in[16];
    const float* gamma  = (const float*)d_in[17];
    float* out = (float*)d_out;
    const float* nul = nullptr;

    // ---- Layer 1 ----
    {
        int total = C1_ * 9 * M_;
        im2col_kernel<<<total / 256, 256>>>(x, msg1, msg2, C1_);
    }
    gemm_kernel<64, 32, 4, 2, 0><<<dim3(M_ / 64, 1), 256>>>(
        w_off1, b_off1, 27, K1_, nullptr, nul, nul, nul, nul, nul, nul);
    gather_kernel<<<B_ * 9 * H_, 256>>>(x, msg1, msg2, C1_);
    gemm_kernel<128, 64, 8, 4, 1><<<dim3(M_ / 128, OC_ / 64), 256>>>(
        w1, nul, OC_, K1_, nullptr, bn1g, bn1b, bn1m, bn1v, nul, nul);

    // ---- Layer 2 ----
    {
        int total = C2_ * 9 * M_;
        im2col_kernel<<<total / 256, 256>>>(nul, nul, nul, C2_);
    }
    gemm_kernel<64, 32, 4, 2, 0><<<dim3(M_ / 64, 1), 256>>>(
        w_off2, b_off2, 27, K2_, nullptr, nul, nul, nul, nul, nul, nul);
    gather_kernel<<<B_ * 9 * H_, 256>>>(nul, nul, nul, C2_);
    gemm_kernel<128, 64, 8, 4, 2><<<dim3(M_ / 128, OC_ / 64), 256>>>(
        w2, nul, OC_, K2_, out, bn2g, bn2b, bn2m, bn2v, x, gamma);
}

// round 3
// speedup vs baseline: 2.6222x; 2.6222x over previous
#include <cuda_runtime.h>
#include <cuda_bf16.h>
#include <cstdint>
#include <math.h>

// Problem constants
#define B_   2
#define H_   64
#define W_   64
#define HW_  4096
#define M_   8192          // B*HW
#define C1_  768
#define C2_  256
#define K1_  6912          // C1*9
#define K2_  2304          // C2*9
#define OC_  256

// ---------------------------------------------------------------------------
// Static scratch
// ---------------------------------------------------------------------------
__device__ float g_V[K1_ * M_];                       // K-major im2col/gather, fp32
__device__ __nv_bfloat16 g_Ah[K1_ * M_];              // A = V^T, pix-major, bf16 hi
__device__ __nv_bfloat16 g_Al[K1_ * M_];              // bf16 lo
__device__ float g_om[B_ * 27 * HW_];
__device__ float g_h1[B_ * OC_ * HW_];
__device__ __nv_bfloat16 g_W1h[OC_ * K1_],  g_W1l[OC_ * K1_];
__device__ __nv_bfloat16 g_WO1h[32 * K1_],  g_WO1l[32 * K1_];
__device__ __nv_bfloat16 g_W2h[OC_ * K2_],  g_W2l[OC_ * K2_];
__device__ __nv_bfloat16 g_WO2h[32 * K2_],  g_WO2l[32 * K2_];

// ---------------------------------------------------------------------------
// PTX helpers (Ampere-era: guaranteed on family target sm_103)
// ---------------------------------------------------------------------------
__device__ __forceinline__ uint32_t smem_u32(const void* p) {
    uint32_t a;
    asm("{ .reg .u64 t; cvta.to.shared.u64 t, %1; cvt.u32.u64 %0, t; }"
        : "=r"(a) : "l"(p));
    return a;
}
__device__ __forceinline__ void ldsm_x4(uint32_t* r, uint32_t addr) {
    asm volatile("ldmatrix.sync.aligned.m8n8.x4.shared.b16 {%0,%1,%2,%3}, [%4];"
                 : "=r"(r[0]), "=r"(r[1]), "=r"(r[2]), "=r"(r[3]) : "r"(addr));
}
__device__ __forceinline__ void mma_bf16(float* c, const uint32_t* a, const uint32_t* b) {
    asm volatile(
        "mma.sync.aligned.m16n8k16.row.col.f32.bf16.bf16.f32 "
        "{%0,%1,%2,%3}, {%4,%5,%6,%7}, {%8,%9}, {%0,%1,%2,%3};"
        : "+f"(c[0]), "+f"(c[1]), "+f"(c[2]), "+f"(c[3])
        : "r"(a[0]), "r"(a[1]), "r"(a[2]), "r"(a[3]), "r"(b[0]), "r"(b[1]));
}

// ---------------------------------------------------------------------------
// im2col: V[(c*9+k)][pix] = src[c][h+ky-1][w+kx-1]  (0-padded)
// ---------------------------------------------------------------------------
__global__ void im2col_kernel(const float* __restrict__ in0,
                              const float* __restrict__ in1,
                              const float* __restrict__ in2,
                              int C) {
    int idx = blockIdx.x * blockDim.x + threadIdx.x;
    int total = C * 9 * M_;
    if (idx >= total) return;
    int p = idx & (M_ - 1);
    int r = idx >> 13;
    int c = r / 9;
    int k = r - c * 9;
    int ky = k / 3 - 1, kx = k % 3 - 1;
    int b = p >> 12, hw = p & 4095;
    int h = hw >> 6, w = hw & 63;
    int y = h + ky, x = w + kx;
    float v = 0.f;
    if (y >= 0 && y < 64 && x >= 0 && x < 64) {
        const float* src;
        if (in0 == nullptr) src = g_h1;
        else src = (c < 256) ? in0 : ((c < 512) ? in1 : in2);
        v = src[((b << 8) + (c & 255)) * HW_ + y * 64 + x];
    }
    g_V[idx] = v;
}

// ---------------------------------------------------------------------------
// Deform gather: overwrite g_V with bilinear-sampled * mask
// ---------------------------------------------------------------------------
__global__ void gather_kernel(const float* __restrict__ in0,
                              const float* __restrict__ in1,
                              const float* __restrict__ in2,
                              int C) {
    int hb = blockIdx.x;
    int h  = hb & 63;
    int bk = hb >> 6;
    int k  = bk % 9;
    int b  = bk / 9;
    int w  = threadIdx.x & 63;
    int cq = threadIdx.x >> 6;

    int ombase = (b * 27) * HW_ + h * 64 + w;
    float dy = g_om[ombase + (2 * k) * HW_];
    float dx = g_om[ombase + (2 * k + 1) * HW_];
    float mk = g_om[ombase + (18 + k) * HW_];
    mk = 1.0f / (1.0f + expf(-mk));

    float ys = dy + (float)h + (float)(k / 3 - 1);
    float xs = dx + (float)w + (float)(k % 3 - 1);
    float y0f = floorf(ys), x0f = floorf(xs);
    float wy = ys - y0f, wx = xs - x0f;
    int y0 = (int)y0f, x0 = (int)x0f;
    int y1 = y0 + 1,  x1 = x0 + 1;
    float vy0 = (y0 >= 0 && y0 < 64) ? 1.f : 0.f;
    float vy1 = (y1 >= 0 && y1 < 64) ? 1.f : 0.f;
    float vx0 = (x0 >= 0 && x0 < 64) ? 1.f : 0.f;
    float vx1 = (x1 >= 0 && x1 < 64) ? 1.f : 0.f;
    int y0c = min(max(y0, 0), 63), y1c = min(max(y1, 0), 63);
    int x0c = min(max(x0, 0), 63), x1c = min(max(x1, 0), 63);
    float w00 = (1.f - wy) * (1.f - wx) * vy0 * vx0;
    float w01 = (1.f - wy) * wx * vy0 * vx1;
    float w10 = wy * (1.f - wx) * vy1 * vx0;
    float w11 = wy * wx * vy1 * vx1;
    int i00 = y0c * 64 + x0c, i01 = y0c * 64 + x1c;
    int i10 = y1c * 64 + x0c, i11 = y1c * 64 + x1c;

    int outbase = k * M_ + b * HW_ + h * 64 + w;
    for (int c = cq; c < C; c += 4) {
        const float* src;
        if (in0 == nullptr) src = g_h1;
        else src = (c < 256) ? in0 : ((c < 512) ? in1 : in2);
        const float* p = src + ((b << 8) + (c & 255)) * HW_;
        float v = w00 * p[i00] + w01 * p[i01] + w10 * p[i10] + w11 * p[i11];
        g_V[outbase + c * 9 * M_] = v * mk;
    }
}

// ---------------------------------------------------------------------------
// Transpose + split: g_V[k][pix] (fp32) -> g_Ah/g_Al[pix][k] (bf16 hi/lo)
// ---------------------------------------------------------------------------
__global__ void transpose_split_kernel(int K) {
    __shared__ float t[32][33];
    int m0 = blockIdx.x * 32;
    int k0 = blockIdx.y * 32;
    int tx = threadIdx.x & 31;
    int ty = threadIdx.x >> 5;   // 0..7
    #pragma unroll
    for (int j = 0; j < 32; j += 8)
        t[ty + j][tx] = g_V[(size_t)(k0 + ty + j) * M_ + m0 + tx];
    __syncthreads();
    #pragma unroll
    for (int j = 0; j < 32; j += 8) {
        float v = t[tx][ty + j];
        __nv_bfloat16 hi = __float2bfloat16(v);
        __nv_bfloat16 lo = __float2bfloat16(v - __bfloat162float(hi));
        size_t o = (size_t)(m0 + ty + j) * K + k0 + tx;
        g_Ah[o] = hi;
        g_Al[o] = lo;
    }
}

// ---------------------------------------------------------------------------
// Weight convert: fp32 [Nsrc][K] -> bf16 hi/lo [Npad][K] (pad rows zero)
// ---------------------------------------------------------------------------
template<int WSEL>
__global__ void wconvert_kernel(const float* __restrict__ w, int K, int Nsrc, int Npad) {
    int i = blockIdx.x * 256 + threadIdx.x;
    if (i >= Npad * K) return;
    int n = i / K;
    float v = (n < Nsrc) ? w[i] : 0.f;
    __nv_bfloat16 hi = __float2bfloat16(v);
    __nv_bfloat16 lo = __float2bfloat16(v - __bfloat162float(hi));
    __nv_bfloat16 *dh, *dl;
    if (WSEL == 0)      { dh = g_WO1h; dl = g_WO1l; }
    else if (WSEL == 1) { dh = g_W1h;  dl = g_W1l;  }
    else if (WSEL == 2) { dh = g_WO2h; dl = g_WO2l; }
    else                { dh = g_W2h;  dl = g_W2l;  }
    dh[i] = hi;
    dl[i] = lo;
}

// ---------------------------------------------------------------------------
// mma.sync bf16 hi/lo GEMM: D[m=128][n=NT] = sum_k A[pix][k] * W[n][k]
//   3-term: Ah*Bh + Al*Bh + Ah*Bl
// MODE 0: g_om = D + bias (n<27);  MODE 1: g_h1 = bn_relu(D);
// MODE 2: out = leaky(resid + gamma*bn_relu(D))
// ---------------------------------------------------------------------------
template<int K, int NT, int WM, int WN, int MODE, int WSEL>
__global__ __launch_bounds__(256, 2)
void mm_gemm_kernel(const float* __restrict__ bias,
                    float* __restrict__ outp,
                    const float* __restrict__ bng, const float* __restrict__ bnb,
                    const float* __restrict__ bnm, const float* __restrict__ bnv,
                    const float* __restrict__ resid, const float* __restrict__ gamma) {
    // SMEM: padded stride 40 halfwords (80B) -> conflict-free ldmatrix
    __shared__ __align__(16) __nv_bfloat16 sAh[128 * 40];
    __shared__ __align__(16) __nv_bfloat16 sAl[128 * 40];
    __shared__ __align__(16) __nv_bfloat16 sBh[NT * 40];
    __shared__ __align__(16) __nv_bfloat16 sBl[NT * 40];

    constexpr int MI = WM / 16;
    constexpr int NJ = WN / 8;
    constexpr int NWn = NT / WN;         // warps along n
    constexpr int MWn = 8 / NWn;         // warps along m

    const int tid = threadIdx.x;
    const int w   = tid >> 5;
    const int l   = tid & 31;
    const int mw  = w % MWn;
    const int nw  = w / MWn;
    const int warp_m = mw * WM;
    const int warp_n = nw * WN;
    const int m0 = blockIdx.x * 128;
    const int n0 = blockIdx.y * NT;

    const __nv_bfloat16 *gWh, *gWl;
    if (WSEL == 0)      { gWh = g_WO1h; gWl = g_WO1l; }
    else if (WSEL == 1) { gWh = g_W1h;  gWl = g_W1l;  }
    else if (WSEL == 2) { gWh = g_WO2h; gWl = g_WO2l; }
    else                { gWh = g_W2h;  gWl = g_W2l;  }

    const uint32_t uAh = smem_u32(sAh);
    const uint32_t uAl = smem_u32(sAl);
    const uint32_t uBh = smem_u32(sBh);
    const uint32_t uBl = smem_u32(sBl);

    float acc[MI][NJ][4];
    #pragma unroll
    for (int i = 0; i < MI; i++)
        #pragma unroll
        for (int j = 0; j < NJ; j++)
            #pragma unroll
            for (int q = 0; q < 4; q++) acc[i][j][q] = 0.f;

    // ldmatrix lane addressing (byte offsets within a BK=32 tile, stride 80B)
    const uint32_t a_row = (uint32_t)(l & 15);
    const uint32_t a_koff = (uint32_t)((l >> 4) * 16);      // +8 halfwords
    const uint32_t b_row = (uint32_t)((l & 7) + ((l >> 4) << 3));
    const uint32_t b_koff = (uint32_t)(((l >> 3) & 1) * 16);

    for (int k0 = 0; k0 < K; k0 += 32) {
        __syncthreads();
        // Load A: 128 rows x 32 bf16 x 2 halves. 512 uint4 per half, 2/thread.
        #pragma unroll
        for (int it = 0; it < 2; it++) {
            int i = tid + it * 256;
            int r = i >> 2, seg = i & 3;
            size_t go = (size_t)(m0 + r) * K + k0 + seg * 8;
            uint32_t so = (uint32_t)(r * 80 + seg * 16);
            *(uint4*)((char*)sAh + so) = *(const uint4*)(g_Ah + go);
            *(uint4*)((char*)sAl + so) = *(const uint4*)(g_Al + go);
        }
        // Load B: NT rows x 32 bf16 x 2 halves.
        if (NT == 128) {
            #pragma unroll
            for (int it = 0; it < 2; it++) {
                int i = tid + it * 256;
                int r = i >> 2, seg = i & 3;
                size_t go = (size_t)(n0 + r) * K + k0 + seg * 8;
                uint32_t so = (uint32_t)(r * 80 + seg * 16);
                *(uint4*)((char*)sBh + so) = *(const uint4*)(gWh + go);
                *(uint4*)((char*)sBl + so) = *(const uint4*)(gWl + go);
            }
        } else {
            if (tid < NT * 4) {
                int r = tid >> 2, seg = tid & 3;
                size_t go = (size_t)(n0 + r) * K + k0 + seg * 8;
                uint32_t so = (uint32_t)(r * 80 + seg * 16);
                *(uint4*)((char*)sBh + so) = *(const uint4*)(gWh + go);
                *(uint4*)((char*)sBl + so) = *(const uint4*)(gWl + go);
            }
        }
        __syncthreads();

        #pragma unroll
        for (int ks = 0; ks < 2; ks++) {
            uint32_t ah[MI][4], al[MI][4];
            #pragma unroll
            for (int i = 0; i < MI; i++) {
                uint32_t off = (uint32_t)((warp_m + i * 16 + a_row) * 80 + ks * 32) + a_koff;
                ldsm_x4(ah[i], uAh + off);
                ldsm_x4(al[i], uAl + off);
            }
            // pass 1: B hi with A hi + A lo
            #pragma unroll
            for (int jj = 0; jj < NJ / 2; jj++) {
                uint32_t b4[4];
                uint32_t off = (uint32_t)((warp_n + jj * 16 + b_row) * 80 + ks * 32) + b_koff;
                ldsm_x4(b4, uBh + off);
                #pragma unroll
                for (int i = 0; i < MI; i++) {
                    mma_bf16(acc[i][jj * 2],     ah[i], b4);
                    mma_bf16(acc[i][jj * 2],     al[i], b4);
                    mma_bf16(acc[i][jj * 2 + 1], ah[i], b4 + 2);
                    mma_bf16(acc[i][jj * 2 + 1], al[i], b4 + 2);
                }
            }
            // pass 2: B lo with A hi only
            #pragma unroll
            for (int jj = 0; jj < NJ / 2; jj++) {
                uint32_t b4[4];
                uint32_t off = (uint32_t)((warp_n + jj * 16 + b_row) * 80 + ks * 32) + b_koff;
                ldsm_x4(b4, uBl + off);
                #pragma unroll
                for (int i = 0; i < MI; i++) {
                    mma_bf16(acc[i][jj * 2],     ah[i], b4);
                    mma_bf16(acc[i][jj * 2 + 1], ah[i], b4 + 2);
                }
            }
        }
    }

    // Epilogue: acc[i][j][q]: m = m0+warp_m+i*16 + (l>>2) + (q>=2 ? 8:0)
    //                         n = n0+warp_n+j*8 + (l&3)*2 + (q&1)
    const float gam = (MODE == 2) ? gamma[0] : 0.f;
    #pragma unroll
    for (int i = 0; i < MI; i++) {
        #pragma unroll
        for (int j = 0; j < NJ; j++) {
            #pragma unroll
            for (int q = 0; q < 4; q++) {
                int m = m0 + warp_m + i * 16 + (l >> 2) + ((q >> 1) << 3);
                int n = n0 + warp_n + j * 8 + (l & 3) * 2 + (q & 1);
                int b  = m >> 12;
                int hw = m & 4095;
                float v = acc[i][j][q];
                if (MODE == 0) {
                    if (n < 27) g_om[(b * 27 + n) * HW_ + hw] = v + bias[n];
                } else {
                    float scale = bng[n] * rsqrtf(bnv[n] + 1e-5f);
                    float shift = bnb[n] - bnm[n] * scale;
                    float t = fmaxf(v * scale + shift, 0.f);
                    int oidx = (b * OC_ + n) * HW_ + hw;
                    if (MODE == 1) {
                        g_h1[oidx] = t;
                    } else {
                        float o = resid[oidx] + gam * t;
                        outp[oidx] = (o >= 0.f) ? o : 0.01f * o;
                    }
                }
            }
        }
    }
}

// ---------------------------------------------------------------------------
extern "C" void kernel_launch(void* const* d_in, const int* in_sizes, int n_in,
                              void* d_out, int out_size) {
    const float* x      = (const float*)d_in[0];
    const float* msg1   = (const float*)d_in[1];
    const float* msg2   = (const float*)d_in[2];
    const float* w_off1 = (const float*)d_in[3];
    const float* b_off1 = (const float*)d_in[4];
    const float* w1     = (const float*)d_in[5];
    const float* bn1g   = (const float*)d_in[6];
    const float* bn1b   = (const float*)d_in[7];
    const float* bn1m   = (const float*)d_in[8];
    const float* bn1v   = (const float*)d_in[9];
    const float* w_off2 = (const float*)d_in[10];
    const float* b_off2 = (const float*)d_in[11];
    const float* w2     = (const float*)d_in[12];
    const float* bn2g   = (const float*)d_in[13];
    const float* bn2b   = (const float*)d_in[14];
    const float* bn2m   = (const float*)d_in[15];
    const float* bn2v   = (const float*)d_in[16];
    const float* gamma  = (const float*)d_in[17];
    float* out = (float*)d_out;
    const float* nul = nullptr;

    // Weight conversions (cheap; could be hoisted but must stay deterministic)
    wconvert_kernel<0><<<(32 * K1_ + 255) / 256, 256>>>(w_off1, K1_, 27, 32);
    wconvert_kernel<1><<<(OC_ * K1_ + 255) / 256, 256>>>(w1, K1_, 256, 256);
    wconvert_kernel<2><<<(32 * K2_ + 255) / 256, 256>>>(w_off2, K2_, 27, 32);
    wconvert_kernel<3><<<(OC_ * K2_ + 255) / 256, 256>>>(w2, K2_, 256, 256);

    // ---- Layer 1 ----
    im2col_kernel<<<C1_ * 9 * M_ / 256, 256>>>(x, msg1, msg2, C1_);
    transpose_split_kernel<<<dim3(M_ / 32, K1_ / 32), 256>>>(K1_);
    mm_gemm_kernel<K1_, 32, 16, 32, 0, 0><<<dim3(M_ / 128, 1), 256>>>(
        b_off1, nullptr, nul, nul, nul, nul, nul, nul);
    gather_kernel<<<B_ * 9 * H_, 256>>>(x, msg1, msg2, C1_);
    transpose_split_kernel<<<dim3(M_ / 32, K1_ / 32), 256>>>(K1_);
    mm_gemm_kernel<K1_, 128, 32, 64, 1, 1><<<dim3(M_ / 128, OC_ / 128), 256>>>(
        nul, nullptr, bn1g, bn1b, bn1m, bn1v, nul, nul);

    // ---- Layer 2 ----
    im2col_kernel<<<C2_ * 9 * M_ / 256, 256>>>(nul, nul, nul, C2_);
    transpose_split_kernel<<<dim3(M_ / 32, K2_ / 32), 256>>>(K2_);
    mm_gemm_kernel<K2_, 32, 16, 32, 0, 2><<<dim3(M_ / 128, 1), 256>>>(
        b_off2, nullptr, nul, nul, nul, nul, nul, nul);
    gather_kernel<<<B_ * 9 * H_, 256>>>(nul, nul, nul, C2_);
    transpose_split_kernel<<<dim3(M_ / 32, K2_ / 32), 256>>>(K2_);
    mm_gemm_kernel<K2_, 128, 32, 64, 2, 3><<<dim3(M_ / 128, OC_ / 128), 256>>>(
        nul, out, bn2g, bn2b, bn2m, bn2v, x, gamma);
}

// round 4
// speedup vs baseline: 4.1107x; 1.5677x over previous
#include <cuda_runtime.h>
#include <cuda_bf16.h>
#include <cstdint>
#include <math.h>

// Problem constants
#define B_   2
#define H_   64
#define W_   64
#define HW_  4096
#define M_   8192          // B*HW
#define C1_  768
#define C2_  256
#define K1_  6912          // C1*9
#define K2_  2304          // C2*9
#define OC_  256

// ---------------------------------------------------------------------------
// Static scratch  (K dimension ordered kk = k*C + c, kernel-position-major)
// ---------------------------------------------------------------------------
__device__ __nv_bfloat16 g_Ah[K1_ * M_];              // A[pix][kk], bf16 hi
__device__ __nv_bfloat16 g_Al[K1_ * M_];              // bf16 lo
__device__ float g_om[B_ * 27 * HW_];
__device__ float g_h1[B_ * OC_ * HW_];
__device__ __nv_bfloat16 g_W1h[OC_ * K1_],  g_W1l[OC_ * K1_];
__device__ __nv_bfloat16 g_WO1h[32 * K1_],  g_WO1l[32 * K1_];
__device__ __nv_bfloat16 g_W2h[OC_ * K2_],  g_W2l[OC_ * K2_];
__device__ __nv_bfloat16 g_WO2h[32 * K2_],  g_WO2l[32 * K2_];

// ---------------------------------------------------------------------------
// PTX helpers (sm_80-era, safe on family target sm_103)
// ---------------------------------------------------------------------------
__device__ __forceinline__ uint32_t smem_u32(const void* p) {
    uint32_t a;
    asm("{ .reg .u64 t; cvta.to.shared.u64 t, %1; cvt.u32.u64 %0, t; }"
        : "=r"(a) : "l"(p));
    return a;
}
__device__ __forceinline__ void ldsm_x4(uint32_t* r, uint32_t addr) {
    asm volatile("ldmatrix.sync.aligned.m8n8.x4.shared.b16 {%0,%1,%2,%3}, [%4];"
                 : "=r"(r[0]), "=r"(r[1]), "=r"(r[2]), "=r"(r[3]) : "r"(addr));
}
__device__ __forceinline__ void mma_bf16(float* c, const uint32_t* a, const uint32_t* b) {
    asm volatile(
        "mma.sync.aligned.m16n8k16.row.col.f32.bf16.bf16.f32 "
        "{%0,%1,%2,%3}, {%4,%5,%6,%7}, {%8,%9}, {%0,%1,%2,%3};"
        : "+f"(c[0]), "+f"(c[1]), "+f"(c[2]), "+f"(c[3])
        : "r"(a[0]), "r"(a[1]), "r"(a[2]), "r"(a[3]), "r"(b[0]), "r"(b[1]));
}
#define CP_ASYNC16(dst, src) \
    asm volatile("cp.async.cg.shared.global [%0], [%1], 16;" :: "r"(dst), "l"(src))
#define CP_COMMIT() asm volatile("cp.async.commit_group;")
#define CP_WAIT(n)  asm volatile("cp.async.wait_group %0;" :: "n"(n))

// ---------------------------------------------------------------------------
// Fused im2col + bf16 split: g_Ah/g_Al[pix][k*C + c] = src[c][h+ky-1][w+kx-1]
// grid (M/32, C/32, 9), block 256 = 32 lanes x 8 rows
// ---------------------------------------------------------------------------
__global__ void im2col_split_kernel(const float* __restrict__ in0,
                                    const float* __restrict__ in1,
                                    const float* __restrict__ in2,
                                    int C, int K) {
    __shared__ float t[32][33];
    const int m0 = blockIdx.x * 32;
    const int c0 = blockIdx.y * 32;
    const int k  = blockIdx.z;
    const int tx = threadIdx.x & 31;
    const int ty = threadIdx.x >> 5;

    const int pix = m0 + tx;
    const int b = pix >> 12, hw = pix & 4095;
    const int h = hw >> 6, w = hw & 63;
    const int y = h + k / 3 - 1, x = w + k % 3 - 1;
    const bool inb = (y >= 0 && y < 64 && x >= 0 && x < 64);

    #pragma unroll
    for (int j = 0; j < 4; j++) {
        int c = c0 + ty + j * 8;
        float v = 0.f;
        if (inb) {
            const float* src;
            if (in0 == nullptr) src = g_h1;
            else src = (c < 256) ? in0 : ((c < 512) ? in1 : in2);
            v = src[((b << 8) + (c & 255)) * HW_ + y * 64 + x];
        }
        t[ty + j * 8][tx] = v;
    }
    __syncthreads();
    #pragma unroll
    for (int j = 0; j < 4; j++) {
        int r = ty + j * 8;                       // pixel row within tile
        float v = t[tx][r];
        __nv_bfloat16 hi = __float2bfloat16(v);
        __nv_bfloat16 lo = __float2bfloat16(v - __bfloat162float(hi));
        size_t o = (size_t)(m0 + r) * K + (size_t)k * C + c0 + tx;
        g_Ah[o] = hi;
        g_Al[o] = lo;
    }
}

// ---------------------------------------------------------------------------
// Fused deform-gather + bf16 split: overwrites g_Ah/g_Al[pix][k*C+c].
// grid = B*9*H blocks; block 256 = 64 w x 4 c-groups; C in chunks of 64.
// ---------------------------------------------------------------------------
__global__ void gather_split_kernel(const float* __restrict__ in0,
                                    const float* __restrict__ in1,
                                    const float* __restrict__ in2,
                                    int C, int K) {
    __shared__ uint32_t s[64][65];
    const int hb = blockIdx.x;
    const int h  = hb & 63;
    const int bk = hb >> 6;
    const int k  = bk % 9;
    const int b  = bk / 9;
    const int tid = threadIdx.x;
    const int w   = tid & 63;
    const int cq  = tid >> 6;           // 0..3

    const int ombase = (b * 27) * HW_ + h * 64 + w;
    const float dy = g_om[ombase + (2 * k) * HW_];
    const float dx = g_om[ombase + (2 * k + 1) * HW_];
    float mk = g_om[ombase + (18 + k) * HW_];
    mk = 1.0f / (1.0f + expf(-mk));

    const float ys = dy + (float)h + (float)(k / 3 - 1);
    const float xs = dx + (float)w + (float)(k % 3 - 1);
    const float y0f = floorf(ys), x0f = floorf(xs);
    const float wy = ys - y0f, wx = xs - x0f;
    const int y0 = (int)y0f, x0 = (int)x0f;
    const int y1 = y0 + 1,  x1 = x0 + 1;
    const float vy0 = (y0 >= 0 && y0 < 64) ? 1.f : 0.f;
    const float vy1 = (y1 >= 0 && y1 < 64) ? 1.f : 0.f;
    const float vx0 = (x0 >= 0 && x0 < 64) ? 1.f : 0.f;
    const float vx1 = (x1 >= 0 && x1 < 64) ? 1.f : 0.f;
    const int y0c = min(max(y0, 0), 63), y1c = min(max(y1, 0), 63);
    const int x0c = min(max(x0, 0), 63), x1c = min(max(x1, 0), 63);
    const float w00 = (1.f - wy) * (1.f - wx) * vy0 * vx0;
    const float w01 = (1.f - wy) * wx * vy0 * vx1;
    const float w10 = wy * (1.f - wx) * vy1 * vx0;
    const float w11 = wy * wx * vy1 * vx1;
    const int i00 = y0c * 64 + x0c, i01 = y0c * 64 + x1c;
    const int i10 = y1c * 64 + x0c, i11 = y1c * 64 + x1c;

    const int pixbase = b * 4096 + h * 64;
    const int wout = tid & 63;          // c' index in write phase
    const int wq   = tid >> 6;

    for (int c0 = 0; c0 < C; c0 += 64) {
        // compute phase: thread (w, cq) covers c = c0+cq+4m
        #pragma unroll 4
        for (int m = 0; m < 16; m++) {
            int c = c0 + cq + 4 * m;
            const float* src;
            if (in0 == nullptr) src = g_h1;
            else src = (c < 256) ? in0 : ((c < 512) ? in1 : in2);
            const float* p = src + ((b << 8) + (c & 255)) * HW_;
            float v = w00 * p[i00] + w01 * p[i01] + w10 * p[i10] + w11 * p[i11];
            v *= mk;
            __nv_bfloat16 hi = __float2bfloat16(v);
            __nv_bfloat16 lo = __float2bfloat16(v - __bfloat162float(hi));
            uint32_t pk = ((uint32_t)__bfloat16_as_ushort(hi) << 16) |
                          (uint32_t)__bfloat16_as_ushort(lo);
            s[w][cq + 4 * m] = pk;
        }
        __syncthreads();
        // write phase: thread (wq, c') writes rows w = wq*16+it, contiguous c
        #pragma unroll 4
        for (int it = 0; it < 16; it++) {
            int ww = wq * 16 + it;
            uint32_t pk = s[ww][wout];
            size_t o = (size_t)(pixbase + ww) * K + (size_t)k * C + c0 + wout;
            g_Ah[o] = __ushort_as_bfloat16((unsigned short)(pk >> 16));
            g_Al[o] = __ushort_as_bfloat16((unsigned short)(pk & 0xFFFF));
        }
        __syncthreads();
    }
}

// ---------------------------------------------------------------------------
// Weight convert + reorder: out[n][k*C+c] = w[n][c][k] (fp32 -> bf16 hi/lo)
// ---------------------------------------------------------------------------
template<int WSEL>
__global__ void wconvert_kernel(const float* __restrict__ w, int C, int K,
                                int Nsrc, int Npad) {
    int i = blockIdx.x * 256 + threadIdx.x;
    if (i >= Npad * K) return;
    int n  = i / K;
    int kk = i - n * K;
    int k  = kk / C;
    int c  = kk - k * C;
    float v = (n < Nsrc) ? w[(size_t)n * K + (size_t)c * 9 + k] : 0.f;
    __nv_bfloat16 hi = __float2bfloat16(v);
    __nv_bfloat16 lo = __float2bfloat16(v - __bfloat162float(hi));
    __nv_bfloat16 *dh, *dl;
    if (WSEL == 0)      { dh = g_WO1h; dl = g_WO1l; }
    else if (WSEL == 1) { dh = g_W1h;  dl = g_W1l;  }
    else if (WSEL == 2) { dh = g_WO2h; dl = g_WO2l; }
    else                { dh = g_W2h;  dl = g_W2l;  }
    dh[i] = hi;
    dl[i] = lo;
}

// ---------------------------------------------------------------------------
// mma.sync bf16 hi/lo GEMM with cp.async double buffering.
// D[m=128][n=NT] = sum_kk A[pix][kk] * W[n][kk]; 3-term split.
// MODE 0: g_om = D + bias (n<27);  MODE 1: g_h1 = bn_relu(D);
// MODE 2: out = leaky(resid + gamma*bn_relu(D))
// ---------------------------------------------------------------------------
template<int K, int NT, int WM, int WN, int MODE, int WSEL>
__global__ __launch_bounds__(256, 2)
void mm_gemm_kernel(const float* __restrict__ bias,
                    float* __restrict__ outp,
                    const float* __restrict__ bng, const float* __restrict__ bnb,
                    const float* __restrict__ bnm, const float* __restrict__ bnv,
                    const float* __restrict__ resid, const float* __restrict__ gamma) {
    extern __shared__ __align__(16) char dsm[];
    constexpr int offAl = 10240;                 // 128*80
    constexpr int offBh = 20480;
    constexpr int offBl = 20480 + NT * 80;
    constexpr int S     = 20480 + NT * 160;      // bytes per buffer
    const uint32_t ub = smem_u32(dsm);

    constexpr int MI = WM / 16;
    constexpr int NJ = WN / 8;
    constexpr int NWn = NT / WN;
    constexpr int MWn = 8 / NWn;

    const int tid = threadIdx.x;
    const int wrp = tid >> 5;
    const int l   = tid & 31;
    const int warp_m = (wrp % MWn) * WM;
    const int warp_n = (wrp / MWn) * WN;
    const int m0 = blockIdx.x * 128;
    const int n0 = blockIdx.y * NT;

    const __nv_bfloat16 *gWh, *gWl;
    if (WSEL == 0)      { gWh = g_WO1h; gWl = g_WO1l; }
    else if (WSEL == 1) { gWh = g_W1h;  gWl = g_W1l;  }
    else if (WSEL == 2) { gWh = g_WO2h; gWl = g_WO2l; }
    else                { gWh = g_W2h;  gWl = g_W2l;  }

    float acc[MI][NJ][4];
    #pragma unroll
    for (int i = 0; i < MI; i++)
        #pragma unroll
        for (int j = 0; j < NJ; j++)
            #pragma unroll
            for (int q = 0; q < 4; q++) acc[i][j][q] = 0.f;

    const uint32_t a_row  = (uint32_t)(l & 15);
    const uint32_t a_koff = (uint32_t)((l >> 4) * 16);
    const uint32_t b_row  = (uint32_t)((l & 7) + ((l >> 4) << 3));
    const uint32_t b_koff = (uint32_t)(((l >> 3) & 1) * 16);

    auto load_tiles = [&](int ch, int buf) {
        const int k0 = ch * 32;
        const uint32_t bb = ub + (uint32_t)buf * S;
        #pragma unroll
        for (int it = 0; it < 2; it++) {
            int i = tid + it * 256;
            int r = i >> 2, seg = i & 3;
            size_t go = (size_t)(m0 + r) * K + k0 + seg * 8;
            uint32_t so = (uint32_t)(r * 80 + seg * 16);
            CP_ASYNC16(bb + so, g_Ah + go);
            CP_ASYNC16(bb + offAl + so, g_Al + go);
        }
        if (NT == 128) {
            #pragma unroll
            for (int it = 0; it < 2; it++) {
                int i = tid + it * 256;
                int r = i >> 2, seg = i & 3;
                size_t go = (size_t)(n0 + r) * K + k0 + seg * 8;
                uint32_t so = (uint32_t)(r * 80 + seg * 16);
                CP_ASYNC16(bb + offBh + so, gWh + go);
                CP_ASYNC16(bb + offBl + so, gWl + go);
            }
        } else {
            if (tid < NT * 4) {
                int r = tid >> 2, seg = tid & 3;
                size_t go = (size_t)(n0 + r) * K + k0 + seg * 8;
                uint32_t so = (uint32_t)(r * 80 + seg * 16);
                CP_ASYNC16(bb + offBh + so, gWh + go);
                CP_ASYNC16(bb + offBl + so, gWl + go);
            }
        }
    };

    constexpr int NCH = K / 32;
    load_tiles(0, 0);
    CP_COMMIT();

    for (int ch = 0; ch < NCH; ch++) {
        const int buf = ch & 1;
        if (ch + 1 < NCH) {
            load_tiles(ch + 1, buf ^ 1);
            CP_COMMIT();
            CP_WAIT(1);
        } else {
            CP_WAIT(0);
        }
        __syncthreads();

        const uint32_t bb = ub + (uint32_t)buf * S;
        #pragma unroll
        for (int ks = 0; ks < 2; ks++) {
            uint32_t ah[MI][4], al[MI][4];
            #pragma unroll
            for (int i = 0; i < MI; i++) {
                uint32_t off = bb + (uint32_t)((warp_m + i * 16 + a_row) * 80 + ks * 32) + a_koff;
                ldsm_x4(ah[i], off);
                ldsm_x4(al[i], off + offAl);
            }
            #pragma unroll
            for (int jj = 0; jj < NJ / 2; jj++) {
                uint32_t b4[4];
                uint32_t off = bb + offBh +
                    (uint32_t)((warp_n + jj * 16 + b_row) * 80 + ks * 32) + b_koff;
                ldsm_x4(b4, off);
                #pragma unroll
                for (int i = 0; i < MI; i++) {
                    mma_bf16(acc[i][jj * 2],     ah[i], b4);
                    mma_bf16(acc[i][jj * 2],     al[i], b4);
                    mma_bf16(acc[i][jj * 2 + 1], ah[i], b4 + 2);
                    mma_bf16(acc[i][jj * 2 + 1], al[i], b4 + 2);
                }
            }
            #pragma unroll
            for (int jj = 0; jj < NJ / 2; jj++) {
                uint32_t b4[4];
                uint32_t off = bb + offBl +
                    (uint32_t)((warp_n + jj * 16 + b_row) * 80 + ks * 32) + b_koff;
                ldsm_x4(b4, off);
                #pragma unroll
                for (int i = 0; i < MI; i++) {
                    mma_bf16(acc[i][jj * 2],     ah[i], b4);
                    mma_bf16(acc[i][jj * 2 + 1], ah[i], b4 + 2);
                }
            }
        }
        __syncthreads();
    }

    // Epilogue
    const float gam = (MODE == 2) ? gamma[0] : 0.f;
    #pragma unroll
    for (int i = 0; i < MI; i++) {
        #pragma unroll
        for (int j = 0; j < NJ; j++) {
            #pragma unroll
            for (int q = 0; q < 4; q++) {
                int m = m0 + warp_m + i * 16 + (l >> 2) + ((q >> 1) << 3);
                int n = n0 + warp_n + j * 8 + (l & 3) * 2 + (q & 1);
                int b  = m >> 12;
                int hw = m & 4095;
                float v = acc[i][j][q];
                if (MODE == 0) {
                    if (n < 27) g_om[(b * 27 + n) * HW_ + hw] = v + bias[n];
                } else {
                    float scale = bng[n] * rsqrtf(bnv[n] + 1e-5f);
                    float shift = bnb[n] - bnm[n] * scale;
                    float t = fmaxf(v * scale + shift, 0.f);
                    int oidx = (b * OC_ + n) * HW_ + hw;
                    if (MODE == 1) {
                        g_h1[oidx] = t;
                    } else {
                        float o = resid[oidx] + gam * t;
                        outp[oidx] = (o >= 0.f) ? o : 0.01f * o;
                    }
                }
            }
        }
    }
}

// ---------------------------------------------------------------------------
extern "C" void kernel_launch(void* const* d_in, const int* in_sizes, int n_in,
                              void* d_out, int out_size) {
    const float* x      = (const float*)d_in[0];
    const float* msg1   = (const float*)d_in[1];
    const float* msg2   = (const float*)d_in[2];
    const float* w_off1 = (const float*)d_in[3];
    const float* b_off1 = (const float*)d_in[4];
    const float* w1     = (const float*)d_in[5];
    const float* bn1g   = (const float*)d_in[6];
    const float* bn1b   = (const float*)d_in[7];
    const float* bn1m   = (const float*)d_in[8];
    const float* bn1v   = (const float*)d_in[9];
    const float* w_off2 = (const float*)d_in[10];
    const float* b_off2 = (const float*)d_in[11];
    const float* w2     = (const float*)d_in[12];
    const float* bn2g   = (const float*)d_in[13];
    const float* bn2b   = (const float*)d_in[14];
    const float* bn2m   = (const float*)d_in[15];
    const float* bn2v   = (const float*)d_in[16];
    const float* gamma  = (const float*)d_in[17];
    float* out = (float*)d_out;
    const float* nul = nullptr;

    constexpr int SM_MAIN = 2 * (20480 + 128 * 160);   // 81920
    constexpr int SM_OFF  = 2 * (20480 + 32 * 160);    // 51200
    static int attr_done = 0;
    cudaFuncSetAttribute(mm_gemm_kernel<K1_, 32, 16, 32, 0, 0>,
                         cudaFuncAttributeMaxDynamicSharedMemorySize, SM_OFF);
    cudaFuncSetAttribute(mm_gemm_kernel<K1_, 128, 32, 64, 1, 1>,
                         cudaFuncAttributeMaxDynamicSharedMemorySize, SM_MAIN);
    cudaFuncSetAttribute(mm_gemm_kernel<K2_, 32, 16, 32, 0, 2>,
                         cudaFuncAttributeMaxDynamicSharedMemorySize, SM_OFF);
    cudaFuncSetAttribute(mm_gemm_kernel<K2_, 128, 32, 64, 2, 3>,
                         cudaFuncAttributeMaxDynamicSharedMemorySize, SM_MAIN);
    (void)attr_done;

    // Weight conversions (with k*C+c reorder)
    wconvert_kernel<0><<<(32 * K1_ + 255) / 256, 256>>>(w_off1, C1_, K1_, 27, 32);
    wconvert_kernel<1><<<(OC_ * K1_ + 255) / 256, 256>>>(w1, C1_, K1_, 256, 256);
    wconvert_kernel<2><<<(32 * K2_ + 255) / 256, 256>>>(w_off2, C2_, K2_, 27, 32);
    wconvert_kernel<3><<<(OC_ * K2_ + 255) / 256, 256>>>(w2, C2_, K2_, 256, 256);

    // ---- Layer 1 ----
    im2col_split_kernel<<<dim3(M_ / 32, C1_ / 32, 9), 256>>>(x, msg1, msg2, C1_, K1_);
    mm_gemm_kernel<K1_, 32, 16, 32, 0, 0><<<dim3(M_ / 128, 1), 256, SM_OFF>>>(
        b_off1, nullptr, nul, nul, nul, nul, nul, nul);
    gather_split_kernel<<<B_ * 9 * H_, 256>>>(x, msg1, msg2, C1_, K1_);
    mm_gemm_kernel<K1_, 128, 32, 64, 1, 1><<<dim3(M_ / 128, OC_ / 128), 256, SM_MAIN>>>(
        nul, nullptr, bn1g, bn1b, bn1m, bn1v, nul, nul);

    // ---- Layer 2 ----
    im2col_split_kernel<<<dim3(M_ / 32, C2_ / 32, 9), 256>>>(nul, nul, nul, C2_, K2_);
    mm_gemm_kernel<K2_, 32, 16, 32, 0, 2><<<dim3(M_ / 128, 1), 256, SM_OFF>>>(
        b_off2, nullptr, nul, nul, nul, nul, nul, nul);
    gather_split_kernel<<<B_ * 9 * H_, 256>>>(nul, nul, nul, C2_, K2_);
    mm_gemm_kernel<K2_, 128, 32, 64, 2, 3><<<dim3(M_ / 128, OC_ / 128), 256, SM_MAIN>>>(
        nul, out, bn2g, bn2b, bn2m, bn2v, x, gamma);
}

// round 5
// speedup vs baseline: 4.6699x; 1.1360x over previous
#include <cuda_runtime.h>
#include <cuda_bf16.h>
#include <cstdint>
#include <math.h>

// Problem constants
#define B_   2
#define H_   64
#define W_   64
#define HW_  4096
#define M_   8192          // B*HW
#define C1_  768
#define C2_  256
#define K1_  6912          // C1*9
#define K2_  2304          // C2*9
#define OC_  256

// ---------------------------------------------------------------------------
// Static scratch  (K dimension ordered kk = k*C + c, kernel-position-major)
// ---------------------------------------------------------------------------
__device__ __nv_bfloat16 g_Ah[K1_ * M_];              // gathered A[pix][kk], bf16 hi
__device__ __nv_bfloat16 g_Al[K1_ * M_];              // bf16 lo
__device__ __nv_bfloat16 g_Xh[C1_ * M_];              // source transposed [pix][c], hi
__device__ __nv_bfloat16 g_Xl[C1_ * M_];              // lo
__device__ float g_om[B_ * 27 * HW_];
__device__ float g_h1[B_ * OC_ * HW_];
__device__ __nv_bfloat16 g_W1h[OC_ * K1_],  g_W1l[OC_ * K1_];
__device__ __nv_bfloat16 g_WO1h[32 * K1_],  g_WO1l[32 * K1_];
__device__ __nv_bfloat16 g_W2h[OC_ * K2_],  g_W2l[OC_ * K2_];
__device__ __nv_bfloat16 g_WO2h[32 * K2_],  g_WO2l[32 * K2_];

// ---------------------------------------------------------------------------
// PTX helpers (sm_80-era, safe on family target sm_103)
// ---------------------------------------------------------------------------
__device__ __forceinline__ uint32_t smem_u32(const void* p) {
    uint32_t a;
    asm("{ .reg .u64 t; cvta.to.shared.u64 t, %1; cvt.u32.u64 %0, t; }"
        : "=r"(a) : "l"(p));
    return a;
}
__device__ __forceinline__ void ldsm_x4(uint32_t* r, uint32_t addr) {
    asm volatile("ldmatrix.sync.aligned.m8n8.x4.shared.b16 {%0,%1,%2,%3}, [%4];"
                 : "=r"(r[0]), "=r"(r[1]), "=r"(r[2]), "=r"(r[3]) : "r"(addr));
}
__device__ __forceinline__ void mma_bf16(float* c, const uint32_t* a, const uint32_t* b) {
    asm volatile(
        "mma.sync.aligned.m16n8k16.row.col.f32.bf16.bf16.f32 "
        "{%0,%1,%2,%3}, {%4,%5,%6,%7}, {%8,%9}, {%0,%1,%2,%3};"
        : "+f"(c[0]), "+f"(c[1]), "+f"(c[2]), "+f"(c[3])
        : "r"(a[0]), "r"(a[1]), "r"(a[2]), "r"(a[3]), "r"(b[0]), "r"(b[1]));
}
#define CP_ASYNC16(dst, src) \
    asm volatile("cp.async.cg.shared.global [%0], [%1], 16;" :: "r"(dst), "l"(src))
#define CP_ASYNC16Z(dst, src, sz) \
    asm volatile("cp.async.cg.shared.global [%0], [%1], 16, %2;" \
        :: "r"(dst), "l"(src), "r"(sz))
#define CP_COMMIT() asm volatile("cp.async.commit_group;")
#define CP_WAIT(n)  asm volatile("cp.async.wait_group %0;" :: "n"(n))

// ---------------------------------------------------------------------------
// Source transpose + bf16 split: g_Xh/g_Xl[pix][c] = src[c-image][pix]
// grid (M/32, C/32), block 256
// ---------------------------------------------------------------------------
__global__ void xpose_split_kernel(const float* __restrict__ in0,
                                   const float* __restrict__ in1,
                                   const float* __restrict__ in2,
                                   int C) {
    __shared__ float t[32][33];
    const int m0 = blockIdx.x * 32;
    const int c0 = blockIdx.y * 32;
    const int tx = threadIdx.x & 31;
    const int ty = threadIdx.x >> 5;

    const int pix = m0 + tx;
    const int b = pix >> 12, hw = pix & 4095;

    #pragma unroll
    for (int j = 0; j < 4; j++) {
        int c = c0 + ty + j * 8;
        const float* src;
        if (in0 == nullptr) src = g_h1;
        else src = (c < 256) ? in0 : ((c < 512) ? in1 : in2);
        t[ty + j * 8][tx] = src[((b << 8) + (c & 255)) * HW_ + hw];
    }
    __syncthreads();
    #pragma unroll
    for (int j = 0; j < 4; j++) {
        int r = ty + j * 8;                 // pixel row within tile
        float v = t[tx][r];
        __nv_bfloat16 hi = __float2bfloat16(v);
        __nv_bfloat16 lo = __float2bfloat16(v - __bfloat162float(hi));
        size_t o = (size_t)(m0 + r) * C + c0 + tx;
        g_Xh[o] = hi;
        g_Xl[o] = lo;
    }
}

// ---------------------------------------------------------------------------
// Fused deform-gather + bf16 split: writes g_Ah/g_Al[pix][k*C+c].
// grid = B*9*H blocks; block 256 = 64 w x 4 c-groups; C in chunks of 64.
// ---------------------------------------------------------------------------
__global__ void gather_split_kernel(const float* __restrict__ in0,
                                    const float* __restrict__ in1,
                                    const float* __restrict__ in2,
                                    int C, int K) {
    __shared__ uint32_t s[64][65];
    const int hb = blockIdx.x;
    const int h  = hb & 63;
    const int bk = hb >> 6;
    const int k  = bk % 9;
    const int b  = bk / 9;
    const int tid = threadIdx.x;
    const int w   = tid & 63;
    const int cq  = tid >> 6;           // 0..3

    const int ombase = (b * 27) * HW_ + h * 64 + w;
    const float dy = g_om[ombase + (2 * k) * HW_];
    const float dx = g_om[ombase + (2 * k + 1) * HW_];
    float mk = g_om[ombase + (18 + k) * HW_];
    mk = 1.0f / (1.0f + expf(-mk));

    const float ys = dy + (float)h + (float)(k / 3 - 1);
    const float xs = dx + (float)w + (float)(k % 3 - 1);
    const float y0f = floorf(ys), x0f = floorf(xs);
    const float wy = ys - y0f, wx = xs - x0f;
    const int y0 = (int)y0f, x0 = (int)x0f;
    const int y1 = y0 + 1,  x1 = x0 + 1;
    const float vy0 = (y0 >= 0 && y0 < 64) ? 1.f : 0.f;
    const float vy1 = (y1 >= 0 && y1 < 64) ? 1.f : 0.f;
    const float vx0 = (x0 >= 0 && x0 < 64) ? 1.f : 0.f;
    const float vx1 = (x1 >= 0 && x1 < 64) ? 1.f : 0.f;
    const int y0c = min(max(y0, 0), 63), y1c = min(max(y1, 0), 63);
    const int x0c = min(max(x0, 0), 63), x1c = min(max(x1, 0), 63);
    const float w00 = (1.f - wy) * (1.f - wx) * vy0 * vx0;
    const float w01 = (1.f - wy) * wx * vy0 * vx1;
    const float w10 = wy * (1.f - wx) * vy1 * vx0;
    const float w11 = wy * wx * vy1 * vx1;
    const int i00 = y0c * 64 + x0c, i01 = y0c * 64 + x1c;
    const int i10 = y1c * 64 + x0c, i11 = y1c * 64 + x1c;

    const int pixbase = b * 4096 + h * 64;
    const int wout = tid & 63;          // c' index in write phase
    const int wq   = tid >> 6;

    for (int c0 = 0; c0 < C; c0 += 64) {
        #pragma unroll 4
        for (int m = 0; m < 16; m++) {
            int c = c0 + cq + 4 * m;
            const float* src;
            if (in0 == nullptr) src = g_h1;
            else src = (c < 256) ? in0 : ((c < 512) ? in1 : in2);
            const float* p = src + ((b << 8) + (c & 255)) * HW_;
            float v = w00 * p[i00] + w01 * p[i01] + w10 * p[i10] + w11 * p[i11];
            v *= mk;
            __nv_bfloat16 hi = __float2bfloat16(v);
            __nv_bfloat16 lo = __float2bfloat16(v - __bfloat162float(hi));
            uint32_t pk = ((uint32_t)__bfloat16_as_ushort(hi) << 16) |
                          (uint32_t)__bfloat16_as_ushort(lo);
            s[w][cq + 4 * m] = pk;
        }
        __syncthreads();
        #pragma unroll 4
        for (int it = 0; it < 16; it++) {
            int ww = wq * 16 + it;
            uint32_t pk = s[ww][wout];
            size_t o = (size_t)(pixbase + ww) * K + (size_t)k * C + c0 + wout;
            g_Ah[o] = __ushort_as_bfloat16((unsigned short)(pk >> 16));
            g_Al[o] = __ushort_as_bfloat16((unsigned short)(pk & 0xFFFF));
        }
        __syncthreads();
    }
}

// ---------------------------------------------------------------------------
// Weight convert + reorder: out[n][k*C+c] = w[n][c][k] (fp32 -> bf16 hi/lo)
// ---------------------------------------------------------------------------
template<int WSEL>
__global__ void wconvert_kernel(const float* __restrict__ w, int C, int K,
                                int Nsrc, int Npad) {
    int i = blockIdx.x * 256 + threadIdx.x;
    if (i >= Npad * K) return;
    int n  = i / K;
    int kk = i - n * K;
    int k  = kk / C;
    int c  = kk - k * C;
    float v = (n < Nsrc) ? w[(size_t)n * K + (size_t)c * 9 + k] : 0.f;
    __nv_bfloat16 hi = __float2bfloat16(v);
    __nv_bfloat16 lo = __float2bfloat16(v - __bfloat162float(hi));
    __nv_bfloat16 *dh, *dl;
    if (WSEL == 0)      { dh = g_WO1h; dl = g_WO1l; }
    else if (WSEL == 1) { dh = g_W1h;  dl = g_W1l;  }
    else if (WSEL == 2) { dh = g_WO2h; dl = g_WO2l; }
    else                { dh = g_W2h;  dl = g_W2l;  }
    dh[i] = hi;
    dl[i] = lo;
}

// ---------------------------------------------------------------------------
// mma.sync bf16 hi/lo GEMM with cp.async double buffering.
// D[m=128][n=NT] = sum_kk A[pix][kk] * W[n][kk]; 3-term split.
// SHIFTED=0: A from g_Ah/g_Al (materialized, [pix][kk]).
// SHIFTED=1: A chunks read from g_Xh/g_Xl[pix][c] with per-kernel-position
//            pixel shift (implicit im2col; C = K/9, chunk never straddles k).
// MODE 0: g_om = D + bias (n<27);  MODE 1: g_h1 = bn_relu(D);
// MODE 2: out = leaky(resid + gamma*bn_relu(D))
// ---------------------------------------------------------------------------
template<int K, int NT, int WM, int WN, int MODE, int WSEL, int SHIFTED>
__global__ __launch_bounds__(256, 2)
void mm_gemm_kernel(const float* __restrict__ bias,
                    float* __restrict__ outp,
                    const float* __restrict__ bng, const float* __restrict__ bnb,
                    const float* __restrict__ bnm, const float* __restrict__ bnv,
                    const float* __restrict__ resid, const float* __restrict__ gamma) {
    extern __shared__ __align__(16) char dsm[];
    constexpr int offAl = 10240;                 // 128*80
    constexpr int offBh = 20480;
    constexpr int offBl = 20480 + NT * 80;
    constexpr int S     = 20480 + NT * 160;      // bytes per buffer
    constexpr int C     = K / 9;                 // channels (SHIFTED mode)
    const uint32_t ub = smem_u32(dsm);

    constexpr int MI = WM / 16;
    constexpr int NJ = WN / 8;
    constexpr int NWn = NT / WN;
    constexpr int MWn = 8 / NWn;

    const int tid = threadIdx.x;
    const int wrp = tid >> 5;
    const int l   = tid & 31;
    const int warp_m = (wrp % MWn) * WM;
    const int warp_n = (wrp / MWn) * WN;
    const int m0 = blockIdx.x * 128;
    const int n0 = blockIdx.y * NT;

    const __nv_bfloat16 *gWh, *gWl;
    if (WSEL == 0)      { gWh = g_WO1h; gWl = g_WO1l; }
    else if (WSEL == 1) { gWh = g_W1h;  gWl = g_W1l;  }
    else if (WSEL == 2) { gWh = g_WO2h; gWl = g_WO2l; }
    else                { gWh = g_W2h;  gWl = g_W2l;  }

    float acc[MI][NJ][4];
    #pragma unroll
    for (int i = 0; i < MI; i++)
        #pragma unroll
        for (int j = 0; j < NJ; j++)
            #pragma unroll
            for (int q = 0; q < 4; q++) acc[i][j][q] = 0.f;

    const uint32_t a_row  = (uint32_t)(l & 15);
    const uint32_t a_koff = (uint32_t)((l >> 4) * 16);
    const uint32_t b_row  = (uint32_t)((l & 7) + ((l >> 4) << 3));
    const uint32_t b_koff = (uint32_t)(((l >> 3) & 1) * 16);

    auto load_tiles = [&](int ch, int buf) {
        const int k0 = ch * 32;
        const uint32_t bb = ub + (uint32_t)buf * S;
        if (SHIFTED) {
            const int kpos = k0 / C;
            const int c0   = k0 - kpos * C;
            const int ky = kpos / 3 - 1, kx = kpos % 3 - 1;
            const int shift = ky * 64 + kx;
            #pragma unroll
            for (int it = 0; it < 2; it++) {
                int i = tid + it * 256;
                int r = i >> 2, seg = i & 3;
                int pix = m0 + r;
                int h = (pix >> 6) & 63, w = pix & 63;
                int y = h + ky, x = w + kx;
                bool ok = (y >= 0 && y < 64 && x >= 0 && x < 64);
                int srcpix = ok ? (pix + shift) : 0;
                int sz = ok ? 16 : 0;
                size_t go = (size_t)srcpix * C + c0 + seg * 8;
                uint32_t so = (uint32_t)(r * 80 + seg * 16);
                CP_ASYNC16Z(bb + so, g_Xh + go, sz);
                CP_ASYNC16Z(bb + offAl + so, g_Xl + go, sz);
            }
        } else {
            #pragma unroll
            for (int it = 0; it < 2; it++) {
                int i = tid + it * 256;
                int r = i >> 2, seg = i & 3;
                size_t go = (size_t)(m0 + r) * K + k0 + seg * 8;
                uint32_t so = (uint32_t)(r * 80 + seg * 16);
                CP_ASYNC16(bb + so, g_Ah + go);
                CP_ASYNC16(bb + offAl + so, g_Al + go);
            }
        }
        if (NT == 128) {
            #pragma unroll
            for (int it = 0; it < 2; it++) {
                int i = tid + it * 256;
                int r = i >> 2, seg = i & 3;
                size_t go = (size_t)(n0 + r) * K + k0 + seg * 8;
                uint32_t so = (uint32_t)(r * 80 + seg * 16);
                CP_ASYNC16(bb + offBh + so, gWh + go);
                CP_ASYNC16(bb + offBl + so, gWl + go);
            }
        } else {
            if (tid < NT * 4) {
                int r = tid >> 2, seg = tid & 3;
                size_t go = (size_t)(n0 + r) * K + k0 + seg * 8;
                uint32_t so = (uint32_t)(r * 80 + seg * 16);
                CP_ASYNC16(bb + offBh + so, gWh + go);
                CP_ASYNC16(bb + offBl + so, gWl + go);
            }
        }
    };

    constexpr int NCH = K / 32;
    load_tiles(0, 0);
    CP_COMMIT();

    for (int ch = 0; ch < NCH; ch++) {
        const int buf = ch & 1;
        if (ch + 1 < NCH) {
            load_tiles(ch + 1, buf ^ 1);
            CP_COMMIT();
            CP_WAIT(1);
        } else {
            CP_WAIT(0);
        }
        __syncthreads();

        const uint32_t bb = ub + (uint32_t)buf * S;
        #pragma unroll
        for (int ks = 0; ks < 2; ks++) {
            uint32_t ah[MI][4], al[MI][4];
            #pragma unroll
            for (int i = 0; i < MI; i++) {
                uint32_t off = bb + (uint32_t)((warp_m + i * 16 + a_row) * 80 + ks * 32) + a_koff;
                ldsm_x4(ah[i], off);
                ldsm_x4(al[i], off + offAl);
            }
            #pragma unroll
            for (int jj = 0; jj < NJ / 2; jj++) {
                uint32_t b4[4];
                uint32_t off = bb + offBh +
                    (uint32_t)((warp_n + jj * 16 + b_row) * 80 + ks * 32) + b_koff;
                ldsm_x4(b4, off);
                #pragma unroll
                for (int i = 0; i < MI; i++) {
                    mma_bf16(acc[i][jj * 2],     ah[i], b4);
                    mma_bf16(acc[i][jj * 2],     al[i], b4);
                    mma_bf16(acc[i][jj * 2 + 1], ah[i], b4 + 2);
                    mma_bf16(acc[i][jj * 2 + 1], al[i], b4 + 2);
                }
            }
            #pragma unroll
            for (int jj = 0; jj < NJ / 2; jj++) {
                uint32_t b4[4];
                uint32_t off = bb + offBl +
                    (uint32_t)((warp_n + jj * 16 + b_row) * 80 + ks * 32) + b_koff;
                ldsm_x4(b4, off);
                #pragma unroll
                for (int i = 0; i < MI; i++) {
                    mma_bf16(acc[i][jj * 2],     ah[i], b4);
                    mma_bf16(acc[i][jj * 2 + 1], ah[i], b4 + 2);
                }
            }
        }
        __syncthreads();
    }

    // Epilogue
    const float gam = (MODE == 2) ? gamma[0] : 0.f;
    #pragma unroll
    for (int i = 0; i < MI; i++) {
        #pragma unroll
        for (int j = 0; j < NJ; j++) {
            #pragma unroll
            for (int q = 0; q < 4; q++) {
                int m = m0 + warp_m + i * 16 + (l >> 2) + ((q >> 1) << 3);
                int n = n0 + warp_n + j * 8 + (l & 3) * 2 + (q & 1);
                int b  = m >> 12;
                int hw = m & 4095;
                float v = acc[i][j][q];
                if (MODE == 0) {
                    if (n < 27) g_om[(b * 27 + n) * HW_ + hw] = v + bias[n];
                } else {
                    float scale = bng[n] * rsqrtf(bnv[n] + 1e-5f);
                    float shift = bnb[n] - bnm[n] * scale;
                    float t = fmaxf(v * scale + shift, 0.f);
                    int oidx = (b * OC_ + n) * HW_ + hw;
                    if (MODE == 1) {
                        g_h1[oidx] = t;
                    } else {
                        float o = resid[oidx] + gam * t;
                        outp[oidx] = (o >= 0.f) ? o : 0.01f * o;
                    }
                }
            }
        }
    }
}

// ---------------------------------------------------------------------------
extern "C" void kernel_launch(void* const* d_in, const int* in_sizes, int n_in,
                              void* d_out, int out_size) {
    const float* x      = (const float*)d_in[0];
    const float* msg1   = (const float*)d_in[1];
    const float* msg2   = (const float*)d_in[2];
    const float* w_off1 = (const float*)d_in[3];
    const float* b_off1 = (const float*)d_in[4];
    const float* w1     = (const float*)d_in[5];
    const float* bn1g   = (const float*)d_in[6];
    const float* bn1b   = (const float*)d_in[7];
    const float* bn1m   = (const float*)d_in[8];
    const float* bn1v   = (const float*)d_in[9];
    const float* w_off2 = (const float*)d_in[10];
    const float* b_off2 = (const float*)d_in[11];
    const float* w2     = (const float*)d_in[12];
    const float* bn2g   = (const float*)d_in[13];
    const float* bn2b   = (const float*)d_in[14];
    const float* bn2m   = (const float*)d_in[15];
    const float* bn2v   = (const float*)d_in[16];
    const float* gamma  = (const float*)d_in[17];
    float* out = (float*)d_out;
    const float* nul = nullptr;

    constexpr int SM_MAIN = 2 * (20480 + 128 * 160);   // 81920
    constexpr int SM_OFF  = 2 * (20480 + 32 * 160);    // 51200
    cudaFuncSetAttribute(mm_gemm_kernel<K1_, 32, 16, 32, 0, 0, 1>,
                         cudaFuncAttributeMaxDynamicSharedMemorySize, SM_OFF);
    cudaFuncSetAttribute(mm_gemm_kernel<K1_, 128, 32, 64, 1, 1, 0>,
                         cudaFuncAttributeMaxDynamicSharedMemorySize, SM_MAIN);
    cudaFuncSetAttribute(mm_gemm_kernel<K2_, 32, 16, 32, 0, 2, 1>,
                         cudaFuncAttributeMaxDynamicSharedMemorySize, SM_OFF);
    cudaFuncSetAttribute(mm_gemm_kernel<K2_, 128, 32, 64, 2, 3, 0>,
                         cudaFuncAttributeMaxDynamicSharedMemorySize, SM_MAIN);

    // Weight conversions (with k*C+c reorder)
    wconvert_kernel<0><<<(32 * K1_ + 255) / 256, 256>>>(w_off1, C1_, K1_, 27, 32);
    wconvert_kernel<1><<<(OC_ * K1_ + 255) / 256, 256>>>(w1, C1_, K1_, 256, 256);
    wconvert_kernel<2><<<(32 * K2_ + 255) / 256, 256>>>(w_off2, C2_, K2_, 27, 32);
    wconvert_kernel<3><<<(OC_ * K2_ + 255) / 256, 256>>>(w2, C2_, K2_, 256, 256);

    // ---- Layer 1 ----
    xpose_split_kernel<<<dim3(M_ / 32, C1_ / 32), 256>>>(x, msg1, msg2, C1_);
    mm_gemm_kernel<K1_, 32, 16, 32, 0, 0, 1><<<dim3(M_ / 128, 1), 256, SM_OFF>>>(
        b_off1, nullptr, nul, nul, nul, nul, nul, nul);
    gather_split_kernel<<<B_ * 9 * H_, 256>>>(x, msg1, msg2, C1_, K1_);
    mm_gemm_kernel<K1_, 128, 32, 64, 1, 1, 0><<<dim3(M_ / 128, OC_ / 128), 256, SM_MAIN>>>(
        nul, nullptr, bn1g, bn1b, bn1m, bn1v, nul, nul);

    // ---- Layer 2 ----
    xpose_split_kernel<<<dim3(M_ / 32, C2_ / 32), 256>>>(nul, nul, nul, C2_);
    mm_gemm_kernel<K2_, 32, 16, 32, 0, 2, 1><<<dim3(M_ / 128, 1), 256, SM_OFF>>>(
        b_off2, nullptr, nul, nul, nul, nul, nul, nul);
    gather_split_kernel<<<B_ * 9 * H_, 256>>>(nul, nul, nul, C2_, K2_);
    mm_gemm_kernel<K2_, 128, 32, 64, 2, 3, 0><<<dim3(M_ / 128, OC_ / 128), 256, SM_MAIN>>>(
        nul, out, bn2g, bn2b, bn2m, bn2v, x, gamma);
}